// round 1
// baseline (speedup 1.0000x reference)
#include <cuda_runtime.h>
#include <cstdint>
#include <cstddef>

// ---------------------------------------------------------------------------
// multilayer_message_passing: 2-layer hetero GraphSAGE
//   per layer, per edge type: h = mean_agg @ Wl^T + x_dst @ Wr^T + b
//   layer 0: relu; every layer: L2-normalize rows; skip: x += h
// Inputs (metadata order):
//   0 x_gene   [100000,128] f32
//   1 x_disease[ 50000,128] f32
//   2 Wl [2,2,128,128] f32   3 Wr [2,2,128,128] f32   4 b [2,2,128] f32
//   5 src_g2d [E] i32  6 dst_g2d [E] i32  7 src_d2g [E] i32  8 dst_d2g [E] i32
// Output: concat(xg [100000*128], xd [50000*128]) f32
// ---------------------------------------------------------------------------

#define N_GENE_MAX 100000
#define N_DIS_MAX   50000
#define DIM 128

// scratch (allocation-free rule: __device__ globals)
__device__ float g_agg_d[(size_t)N_DIS_MAX  * DIM];
__device__ float g_agg_g[(size_t)N_GENE_MAX * DIM];
__device__ float g_cnt_d[N_DIS_MAX];
__device__ float g_cnt_g[N_GENE_MAX];

// ---------------------------------------------------------------------------
__global__ void zero_kernel(float* __restrict__ p, size_t n) {
    size_t i = (size_t)blockIdx.x * blockDim.x + threadIdx.x;
    size_t stride = (size_t)gridDim.x * blockDim.x;
    for (; i < n; i += stride) p[i] = 0.0f;
}

__global__ void count_kernel(const int* __restrict__ dst, float* __restrict__ cnt, int E) {
    int e = blockIdx.x * blockDim.x + threadIdx.x;
    if (e < E) atomicAdd(&cnt[dst[e]], 1.0f);
}

// warp per edge: lane l handles floats [4l, 4l+4) of the 128-dim feature
__global__ void scatter_kernel(const float* __restrict__ xsrc,
                               const int* __restrict__ src,
                               const int* __restrict__ dst,
                               float* __restrict__ agg, int E) {
    int gid  = blockIdx.x * blockDim.x + threadIdx.x;
    int e    = gid >> 5;
    int lane = gid & 31;
    if (e >= E) return;
    int s = src[e];
    int d = dst[e];
    float4 v = ((const float4*)(xsrc + (size_t)s * DIM))[lane];
    float* out = agg + (size_t)d * DIM + lane * 4;
    // sm_90+ vector reduction: 1 instr instead of 4 scalar atomics
    asm volatile("red.global.add.v4.f32 [%0], {%1, %2, %3, %4};"
                 :: "l"(out), "f"(v.x), "f"(v.y), "f"(v.z), "f"(v.w)
                 : "memory");
}

// ---------------------------------------------------------------------------
// Fused: h = (agg/max(cnt,1)) @ Wl^T + x @ Wr^T + b ; relu?; l2norm; x = h + x
// Tile: 64 nodes x 128 outputs per block, 256 threads, micro-tile 4x8.
// ---------------------------------------------------------------------------
#define TM   64
#define PADZ 132
#define PADW 132
#define SMEM_UPD ((TM * PADZ + DIM * PADW) * sizeof(float))

__global__ void __launch_bounds__(256)
update_kernel(const float* __restrict__ agg, const float* __restrict__ cnt,
              float* __restrict__ x,
              const float* __restrict__ Wl, const float* __restrict__ Wr,
              const float* __restrict__ bias,
              int n, int do_relu) {
    extern __shared__ float smem[];
    float* sz = smem;              // [TM][PADZ] : z tile (node-major)
    float* sw = smem + TM * PADZ;  // [DIM(k)][PADW] : W transposed

    const int t     = threadIdx.x;
    const int tile  = blockIdx.x * TM;
    const int tx    = t & 15;    // output group
    const int ty    = t >> 4;    // node group
    const int j0    = tx * 8;
    const int node0 = ty * 4;

    float acc[4][8];
#pragma unroll
    for (int a = 0; a < 4; a++)
#pragma unroll
        for (int q = 0; q < 8; q++) acc[a][q] = 0.0f;

    for (int phase = 0; phase < 2; phase++) {
        const float* W = (phase == 0) ? Wl : Wr;

        // load z tile: phase 0 -> mean-agg, phase 1 -> x (old)
        for (int e = t; e < TM * DIM; e += 256) {
            int nn = e >> 7;
            int k  = e & 127;
            int ng = tile + nn;
            float v = 0.0f;
            if (ng < n) {
                if (phase == 0) {
                    float inv = 1.0f / fmaxf(cnt[ng], 1.0f);
                    v = agg[(size_t)ng * DIM + k] * inv;
                } else {
                    v = x[(size_t)ng * DIM + k];
                }
            }
            sz[nn * PADZ + k] = v;
        }
        // load W transposed: sw[k][j] = W[j][k]
        for (int e = t; e < DIM * DIM; e += 256) {
            int j = e >> 7;
            int k = e & 127;
            sw[k * PADW + j] = W[e];
        }
        __syncthreads();

#pragma unroll 4
        for (int k = 0; k < DIM; k++) {
            float zv[4];
#pragma unroll
            for (int a = 0; a < 4; a++) zv[a] = sz[(node0 + a) * PADZ + k];
            float4 w0 = *(const float4*)(sw + k * PADW + j0);
            float4 w1 = *(const float4*)(sw + k * PADW + j0 + 4);
            float wv[8] = {w0.x, w0.y, w0.z, w0.w, w1.x, w1.y, w1.z, w1.w};
#pragma unroll
            for (int a = 0; a < 4; a++)
#pragma unroll
                for (int q = 0; q < 8; q++) acc[a][q] += zv[a] * wv[q];
        }
        __syncthreads();  // protect sz/sw before next phase's loads
    }

    // epilogue: + bias, relu?, per-node L2 norm (reduce across 16 tx threads),
    // skip-sum with old x (still resident in sz from phase 1), store.
    float bb[8];
#pragma unroll
    for (int q = 0; q < 8; q++) bb[q] = bias[j0 + q];

#pragma unroll
    for (int a = 0; a < 4; a++) {
        float h[8];
        float ssq = 0.0f;
#pragma unroll
        for (int q = 0; q < 8; q++) {
            float v = acc[a][q] + bb[q];
            if (do_relu) v = fmaxf(v, 0.0f);
            h[q] = v;
            ssq += v * v;
        }
#pragma unroll
        for (int m = 1; m < 16; m <<= 1)
            ssq += __shfl_xor_sync(0xffffffffu, ssq, m);
        float scale = 1.0f / fmaxf(sqrtf(ssq), 1e-12f);

        int nn = node0 + a;
        int ng = tile + nn;
        if (ng < n) {
            float4 r0, r1;
            r0.x = h[0] * scale + sz[nn * PADZ + j0 + 0];
            r0.y = h[1] * scale + sz[nn * PADZ + j0 + 1];
            r0.z = h[2] * scale + sz[nn * PADZ + j0 + 2];
            r0.w = h[3] * scale + sz[nn * PADZ + j0 + 3];
            r1.x = h[4] * scale + sz[nn * PADZ + j0 + 4];
            r1.y = h[5] * scale + sz[nn * PADZ + j0 + 5];
            r1.z = h[6] * scale + sz[nn * PADZ + j0 + 6];
            r1.w = h[7] * scale + sz[nn * PADZ + j0 + 7];
            *(float4*)(x + (size_t)ng * DIM + j0)     = r0;
            *(float4*)(x + (size_t)ng * DIM + j0 + 4) = r1;
        }
    }
}

// ---------------------------------------------------------------------------
extern "C" void kernel_launch(void* const* d_in, const int* in_sizes, int n_in,
                              void* d_out, int out_size) {
    const float* x_gene  = (const float*)d_in[0];
    const float* x_dis   = (const float*)d_in[1];
    const float* Wl      = (const float*)d_in[2];
    const float* Wr      = (const float*)d_in[3];
    const float* b       = (const float*)d_in[4];
    const int*   src_g2d = (const int*)d_in[5];
    const int*   dst_g2d = (const int*)d_in[6];
    const int*   src_d2g = (const int*)d_in[7];
    const int*   dst_d2g = (const int*)d_in[8];

    const int n_gene = in_sizes[0] / DIM;
    const int n_dis  = in_sizes[1] / DIM;
    const int E1 = in_sizes[5];  // g2d
    const int E2 = in_sizes[7];  // d2g

    float *agg_d, *agg_g, *cnt_d, *cnt_g;
    cudaGetSymbolAddress((void**)&agg_d, g_agg_d);
    cudaGetSymbolAddress((void**)&agg_g, g_agg_g);
    cudaGetSymbolAddress((void**)&cnt_d, g_cnt_d);
    cudaGetSymbolAddress((void**)&cnt_g, g_cnt_g);

    float* xg = (float*)d_out;
    float* xd = xg + (size_t)n_gene * DIM;

    cudaMemcpyAsync(xg, x_gene, (size_t)n_gene * DIM * sizeof(float),
                    cudaMemcpyDeviceToDevice, 0);
    cudaMemcpyAsync(xd, x_dis, (size_t)n_dis * DIM * sizeof(float),
                    cudaMemcpyDeviceToDevice, 0);

    // degree counts (reused by both layers)
    zero_kernel<<<256, 256>>>(cnt_d, (size_t)n_dis);
    zero_kernel<<<256, 256>>>(cnt_g, (size_t)n_gene);
    count_kernel<<<(E1 + 255) / 256, 256>>>(dst_g2d, cnt_d, E1);
    count_kernel<<<(E2 + 255) / 256, 256>>>(dst_d2g, cnt_g, E2);

    cudaFuncSetAttribute(update_kernel,
                         cudaFuncAttributeMaxDynamicSharedMemorySize,
                         (int)SMEM_UPD);

    const unsigned sc_blocks1 = (unsigned)(((size_t)E1 * 32 + 255) / 256);
    const unsigned sc_blocks2 = (unsigned)(((size_t)E2 * 32 + 255) / 256);

    for (int i = 0; i < 2; i++) {
        zero_kernel<<<1024, 256>>>(agg_d, (size_t)n_dis * DIM);
        zero_kernel<<<1024, 256>>>(agg_g, (size_t)n_gene * DIM);

        // both scatters read the PRE-layer state; updates run after both
        scatter_kernel<<<sc_blocks1, 256>>>(xg, src_g2d, dst_g2d, agg_d, E1);
        scatter_kernel<<<sc_blocks2, 256>>>(xd, src_d2g, dst_d2g, agg_g, E2);

        const float* Wl_d = Wl + (size_t)(i * 2 + 0) * DIM * DIM;
        const float* Wr_d = Wr + (size_t)(i * 2 + 0) * DIM * DIM;
        const float* b_d  = b  + (size_t)(i * 2 + 0) * DIM;
        const float* Wl_g = Wl + (size_t)(i * 2 + 1) * DIM * DIM;
        const float* Wr_g = Wr + (size_t)(i * 2 + 1) * DIM * DIM;
        const float* b_g  = b  + (size_t)(i * 2 + 1) * DIM;

        update_kernel<<<(n_dis + TM - 1) / TM, 256, SMEM_UPD>>>(
            agg_d, cnt_d, xd, Wl_d, Wr_d, b_d, n_dis, i == 0 ? 1 : 0);
        update_kernel<<<(n_gene + TM - 1) / TM, 256, SMEM_UPD>>>(
            agg_g, cnt_g, xg, Wl_g, Wr_g, b_g, n_gene, i == 0 ? 1 : 0);
    }
}

// round 3
// speedup vs baseline: 1.1930x; 1.1930x over previous
#include <cuda_runtime.h>
#include <cuda_bf16.h>
#include <cstdint>
#include <cstddef>

// ---------------------------------------------------------------------------
// multilayer_message_passing: 2-layer hetero GraphSAGE.
// Update GEMM via mma.sync.m16n8k16 bf16 (3-term hi/lo split for fp32 accuracy).
// ---------------------------------------------------------------------------

#define N_GENE_MAX 100000
#define N_DIS_MAX   50000
#define DIM 128

__device__ float g_agg_d[(size_t)N_DIS_MAX  * DIM];
__device__ float g_agg_g[(size_t)N_GENE_MAX * DIM];
__device__ float g_cnt_d[N_DIS_MAX];
__device__ float g_cnt_g[N_GENE_MAX];
// bf16 hi/lo images of the 8 weight matrices, plain [j][k] row-major
// index: ((layer*2+type)*2 + which)*2 + half
__device__ __align__(16) __nv_bfloat16 g_wimg[16][DIM * DIM];

// ---------------------------------------------------------------------------
__device__ __forceinline__ uint32_t smem_u32(const void* p) {
    uint32_t a;
    asm("{ .reg .u64 t; cvta.to.shared.u64 t, %1; cvt.u32.u64 %0, t; }" : "=r"(a) : "l"(p));
    return a;
}

#define LDMX4(r, addr)                                                         \
    asm volatile("ldmatrix.sync.aligned.m8n8.x4.shared.b16 {%0,%1,%2,%3}, [%4];" \
                 : "=r"((r)[0]), "=r"((r)[1]), "=r"((r)[2]), "=r"((r)[3])      \
                 : "r"(addr))

#define MMA16816(d, a, b0, b1)                                                 \
    asm volatile("mma.sync.aligned.m16n8k16.row.col.f32.bf16.bf16.f32 "        \
                 "{%0,%1,%2,%3}, {%4,%5,%6,%7}, {%8,%9}, {%0,%1,%2,%3};"       \
                 : "+f"((d)[0]), "+f"((d)[1]), "+f"((d)[2]), "+f"((d)[3])      \
                 : "r"((a)[0]), "r"((a)[1]), "r"((a)[2]), "r"((a)[3]),         \
                   "r"(b0), "r"(b1))

// ---------------------------------------------------------------------------
__global__ void zero_kernel(float* __restrict__ p, size_t n) {
    size_t i = (size_t)blockIdx.x * blockDim.x + threadIdx.x;
    size_t stride = (size_t)gridDim.x * blockDim.x;
    for (; i < n; i += stride) p[i] = 0.0f;
}

__global__ void count_kernel(const int* __restrict__ dst, float* __restrict__ cnt, int E) {
    int e = blockIdx.x * blockDim.x + threadIdx.x;
    if (e < E) atomicAdd(&cnt[dst[e]], 1.0f);
}

// warp per edge: lane l handles floats [4l, 4l+4)
__global__ void scatter_kernel(const float* __restrict__ xsrc,
                               const int* __restrict__ src,
                               const int* __restrict__ dst,
                               float* __restrict__ agg, int E) {
    int gid  = blockIdx.x * blockDim.x + threadIdx.x;
    int e    = gid >> 5;
    int lane = gid & 31;
    if (e >= E) return;
    int s = src[e];
    int d = dst[e];
    float4 v = ((const float4*)(xsrc + (size_t)s * DIM))[lane];
    float* out = agg + (size_t)d * DIM + lane * 4;
    asm volatile("red.global.add.v4.f32 [%0], {%1, %2, %3, %4};"
                 :: "l"(out), "f"(v.x), "f"(v.y), "f"(v.z), "f"(v.w) : "memory");
}

// bf16 hi/lo images of all 8 weight matrices (plain row-major)
__global__ void prep_w_kernel(const float* __restrict__ Wl, const float* __restrict__ Wr) {
    int mat = blockIdx.x;            // 0..7 = lt*2 + which
    int lt = mat >> 1, which = mat & 1;
    const float* W = (which ? Wr : Wl) + (size_t)lt * DIM * DIM;
    __nv_bfloat16* ih = g_wimg[mat * 2 + 0];
    __nv_bfloat16* il = g_wimg[mat * 2 + 1];
    for (int i = threadIdx.x; i < DIM * DIM; i += blockDim.x) {
        float w = W[i];
        __nv_bfloat16 h = __float2bfloat16(w);
        ih[i] = h;
        il[i] = __float2bfloat16(w - __bfloat162float(h));
    }
}

// ---------------------------------------------------------------------------
// update: 128 nodes x 128 outputs per CTA, 8 warps (4x2), warp tile 32x64.
// D = zh@Wh^T + zl@Wh^T + zh@Wl^T  (per phase; phase0 = mean-agg/Wl, phase1 = x/Wr)
// then +bias, relu?, row-L2norm, x += h.
// SMEM tiles padded: bf16 row stride 136 elems (272 B).
// ---------------------------------------------------------------------------
#define ZSTRIDE 136
#define TILE_B  (128 * ZSTRIDE * 2)   // 34816 bytes per bf16 tile
#define OFF_BIAS 0
#define OFF_ZH   1024
#define OFF_ZL   (OFF_ZH + TILE_B)
#define OFF_WH   (OFF_ZL + TILE_B)
#define OFF_WL   (OFF_WH + TILE_B)
#define SMEM_TOT (OFF_WL + TILE_B)    // 140288 bytes
#define HSTRIDE  132                  // f32 epilogue stride

__global__ void __launch_bounds__(256)
update_kernel(const float* __restrict__ agg, const float* __restrict__ cnt,
              float* __restrict__ x,
              const __nv_bfloat16* __restrict__ wl_hi, const __nv_bfloat16* __restrict__ wl_lo,
              const __nv_bfloat16* __restrict__ wr_hi, const __nv_bfloat16* __restrict__ wr_lo,
              const float* __restrict__ bias, int n, int do_relu) {
    extern __shared__ __align__(16) unsigned char smem[];
    const uint32_t sbase = smem_u32(smem);
    const int t    = threadIdx.x;
    const int wid  = t >> 5;
    const int lane = t & 31;
    const int wm   = wid >> 1;      // 0..3 -> rows
    const int wn   = wid & 1;       // 0..1 -> cols
    const int r0   = wm * 32;
    const int tile = blockIdx.x * 128;

    float* sbias = (float*)(smem + OFF_BIAS);
    if (t < 128) sbias[t] = bias[t];

    // per-lane ldmatrix byte offsets (within a tile)
    const uint32_t aoff =
        ((uint32_t)((r0 + ((lane >> 3) & 1) * 8 + (lane & 7)) * ZSTRIDE +
                    ((lane >> 4) & 1) * 8)) * 2;
    const uint32_t boff =
        ((uint32_t)((wn * 64 + ((lane >> 4) & 1) * 8 + (lane & 7)) * ZSTRIDE +
                    ((lane >> 3) & 1) * 8)) * 2;

    float acc[2][8][4];
#pragma unroll
    for (int f = 0; f < 2; f++)
#pragma unroll
        for (int j = 0; j < 8; j++)
#pragma unroll
            for (int c = 0; c < 4; c++) acc[f][j][c] = 0.0f;

    for (int phase = 0; phase < 2; phase++) {
        // ---- stage z tile (hi/lo bf16, padded) ----
        {
            const int k = t & 127;
            __nv_bfloat16* zh = (__nv_bfloat16*)(smem + OFF_ZH);
            __nv_bfloat16* zl = (__nv_bfloat16*)(smem + OFF_ZL);
            for (int row = (t >> 7); row < 128; row += 2) {
                int ng = tile + row;
                float v = 0.0f;
                if (ng < n) {
                    if (phase == 0) v = agg[(size_t)ng * DIM + k] * (1.0f / fmaxf(cnt[ng], 1.0f));
                    else            v = x[(size_t)ng * DIM + k];
                }
                __nv_bfloat16 h = __float2bfloat16(v);
                zh[row * ZSTRIDE + k] = h;
                zl[row * ZSTRIDE + k] = __float2bfloat16(v - __bfloat162float(h));
            }
        }
        // ---- stage W tiles (hi + lo), global plain -> smem padded ----
        {
            const uint4* gh = (const uint4*)(phase == 0 ? wl_hi : wr_hi);
            const uint4* gl = (const uint4*)(phase == 0 ? wl_lo : wr_lo);
            for (int i = t; i < 2048; i += 256) {     // 16B chunks: j = i>>4, k8 = i&15
                int j = i >> 4, kc = i & 15;
                uint32_t off = ((uint32_t)(j * ZSTRIDE + kc * 8)) * 2;
                *(uint4*)(smem + OFF_WH + off) = gh[i];
                *(uint4*)(smem + OFF_WL + off) = gl[i];
            }
        }
        __syncthreads();

        const uint32_t zh_a = sbase + OFF_ZH + aoff;
        const uint32_t wh_b = sbase + OFF_WH + boff;

#pragma unroll
        for (int ks = 0; ks < 8; ks++) {
            uint32_t azh[2][4], azl[2][4], bh[4][4], bl[4][4];
#pragma unroll
            for (int f = 0; f < 2; f++) {
                uint32_t a = zh_a + ks * 32 + f * (16 * ZSTRIDE * 2);
                LDMX4(azh[f], a);
                LDMX4(azl[f], a + TILE_B);
            }
#pragma unroll
            for (int q = 0; q < 4; q++) {
                uint32_t a = wh_b + ks * 32 + q * (16 * ZSTRIDE * 2);
                LDMX4(bh[q], a);
                LDMX4(bl[q], a + TILE_B);
            }
#pragma unroll
            for (int f = 0; f < 2; f++)
#pragma unroll
                for (int j = 0; j < 8; j++) {
                    const int q = j >> 1, s = (j & 1) * 2;
                    MMA16816(acc[f][j], azh[f], bh[q][s], bh[q][s + 1]);  // zh*Wh
                    MMA16816(acc[f][j], azl[f], bh[q][s], bh[q][s + 1]);  // zl*Wh
                    MMA16816(acc[f][j], azh[f], bl[q][s], bl[q][s + 1]);  // zh*Wl
                }
        }
        __syncthreads();   // tiles reused next phase / by epilogue
    }

    // ---- epilogue: acc -> smem f32, then row L2-norm + skipsum ----
    float* sh = (float*)(smem + OFF_ZH);   // 128 x HSTRIDE f32 (67584 B, fits in zh+zl)
#pragma unroll
    for (int f = 0; f < 2; f++) {
        int row = r0 + f * 16 + (lane >> 2);
        int col = wn * 64 + (lane & 3) * 2;
#pragma unroll
        for (int j = 0; j < 8; j++) {
            int c = col + j * 8;
            sh[row * HSTRIDE + c]           = acc[f][j][0];
            sh[row * HSTRIDE + c + 1]       = acc[f][j][1];
            sh[(row + 8) * HSTRIDE + c]     = acc[f][j][2];
            sh[(row + 8) * HSTRIDE + c + 1] = acc[f][j][3];
        }
    }
    __syncthreads();

    {
        const int row  = t >> 1;
        const int half = t & 1;
        const int c0   = half * 64;
        float ssq = 0.0f;
        float h[64];
#pragma unroll
        for (int c = 0; c < 64; c++) {
            float v = sh[row * HSTRIDE + c0 + c] + sbias[c0 + c];
            if (do_relu) v = fmaxf(v, 0.0f);
            h[c] = v;
            ssq += v * v;
        }
        ssq += __shfl_xor_sync(0xffffffffu, ssq, 1);
        float sc = 1.0f / fmaxf(sqrtf(ssq), 1e-12f);

        int node = tile + row;
        if (node < n) {
            float4* xr = (float4*)(x + (size_t)node * DIM + c0);
#pragma unroll
            for (int q = 0; q < 16; q++) {
                float4 o = xr[q];
                o.x += h[q * 4 + 0] * sc;
                o.y += h[q * 4 + 1] * sc;
                o.z += h[q * 4 + 2] * sc;
                o.w += h[q * 4 + 3] * sc;
                xr[q] = o;
            }
        }
    }
}

// ---------------------------------------------------------------------------
extern "C" void kernel_launch(void* const* d_in, const int* in_sizes, int n_in,
                              void* d_out, int out_size) {
    const float* x_gene  = (const float*)d_in[0];
    const float* x_dis   = (const float*)d_in[1];
    const float* Wl      = (const float*)d_in[2];
    const float* Wr      = (const float*)d_in[3];
    const float* b       = (const float*)d_in[4];
    const int*   src_g2d = (const int*)d_in[5];
    const int*   dst_g2d = (const int*)d_in[6];
    const int*   src_d2g = (const int*)d_in[7];
    const int*   dst_d2g = (const int*)d_in[8];

    const int n_gene = in_sizes[0] / DIM;
    const int n_dis  = in_sizes[1] / DIM;
    const int E1 = in_sizes[5];
    const int E2 = in_sizes[7];

    float *agg_d, *agg_g, *cnt_d, *cnt_g;
    __nv_bfloat16* wimg;
    cudaGetSymbolAddress((void**)&agg_d, g_agg_d);
    cudaGetSymbolAddress((void**)&agg_g, g_agg_g);
    cudaGetSymbolAddress((void**)&cnt_d, g_cnt_d);
    cudaGetSymbolAddress((void**)&cnt_g, g_cnt_g);
    cudaGetSymbolAddress((void**)&wimg, g_wimg);

    float* xg = (float*)d_out;
    float* xd = xg + (size_t)n_gene * DIM;

    cudaMemcpyAsync(xg, x_gene, (size_t)n_gene * DIM * sizeof(float),
                    cudaMemcpyDeviceToDevice, 0);
    cudaMemcpyAsync(xd, x_dis, (size_t)n_dis * DIM * sizeof(float),
                    cudaMemcpyDeviceToDevice, 0);

    prep_w_kernel<<<8, 256>>>(Wl, Wr);

    zero_kernel<<<256, 256>>>(cnt_d, (size_t)n_dis);
    zero_kernel<<<256, 256>>>(cnt_g, (size_t)n_gene);
    count_kernel<<<(E1 + 255) / 256, 256>>>(dst_g2d, cnt_d, E1);
    count_kernel<<<(E2 + 255) / 256, 256>>>(dst_d2g, cnt_g, E2);

    cudaFuncSetAttribute(update_kernel,
                         cudaFuncAttributeMaxDynamicSharedMemorySize, SMEM_TOT);

    const unsigned sc_blocks1 = (unsigned)(((size_t)E1 * 32 + 255) / 256);
    const unsigned sc_blocks2 = (unsigned)(((size_t)E2 * 32 + 255) / 256);

    for (int i = 0; i < 2; i++) {
        zero_kernel<<<1024, 256>>>(agg_d, (size_t)n_dis * DIM);
        zero_kernel<<<1024, 256>>>(agg_g, (size_t)n_gene * DIM);

        scatter_kernel<<<sc_blocks1, 256>>>(xg, src_g2d, dst_g2d, agg_d, E1);
        scatter_kernel<<<sc_blocks2, 256>>>(xd, src_d2g, dst_d2g, agg_g, E2);

        const __nv_bfloat16* p = wimg;
        const __nv_bfloat16* wl_hi_d = p + (size_t)(((i * 2 + 0) * 2 + 0) * 2 + 0) * DIM * DIM;
        const __nv_bfloat16* wl_lo_d = p + (size_t)(((i * 2 + 0) * 2 + 0) * 2 + 1) * DIM * DIM;
        const __nv_bfloat16* wr_hi_d = p + (size_t)(((i * 2 + 0) * 2 + 1) * 2 + 0) * DIM * DIM;
        const __nv_bfloat16* wr_lo_d = p + (size_t)(((i * 2 + 0) * 2 + 1) * 2 + 1) * DIM * DIM;
        const __nv_bfloat16* wl_hi_g = p + (size_t)(((i * 2 + 1) * 2 + 0) * 2 + 0) * DIM * DIM;
        const __nv_bfloat16* wl_lo_g = p + (size_t)(((i * 2 + 1) * 2 + 0) * 2 + 1) * DIM * DIM;
        const __nv_bfloat16* wr_hi_g = p + (size_t)(((i * 2 + 1) * 2 + 1) * 2 + 0) * DIM * DIM;
        const __nv_bfloat16* wr_lo_g = p + (size_t)(((i * 2 + 1) * 2 + 1) * 2 + 1) * DIM * DIM;
        const float* b_d = b + (size_t)(i * 2 + 0) * DIM;
        const float* b_g = b + (size_t)(i * 2 + 1) * DIM;

        update_kernel<<<(n_dis + 127) / 128, 256, SMEM_TOT>>>(
            agg_d, cnt_d, xd, wl_hi_d, wl_lo_d, wr_hi_d, wr_lo_d, b_d, n_dis, i == 0 ? 1 : 0);
        update_kernel<<<(n_gene + 127) / 128, 256, SMEM_TOT>>>(
            agg_g, cnt_g, xg, wl_hi_g, wl_lo_g, wr_hi_g, wr_lo_g, b_g, n_gene, i == 0 ? 1 : 0);
    }
}

// round 4
// speedup vs baseline: 1.8199x; 1.5254x over previous
#include <cuda_runtime.h>
#include <cuda_bf16.h>
#include <cstdint>
#include <cstddef>

// ---------------------------------------------------------------------------
// multilayer_message_passing: 2-layer hetero GraphSAGE.
// R4: pull-mode CSR aggregation (no atomics in steady state, no agg zeroing),
//     mma.sync bf16 3-term hi/lo GEMM update (unchanged from R3).
// ---------------------------------------------------------------------------

#define N_GENE_MAX 100000
#define N_DIS_MAX   50000
#define DIM 128
#define E_MAX 800000

__device__ float g_agg_d[(size_t)N_DIS_MAX  * DIM];
__device__ float g_agg_g[(size_t)N_GENE_MAX * DIM];
__device__ int g_cnt_d[N_DIS_MAX];
__device__ int g_cnt_g[N_GENE_MAX];
__device__ int g_off_d[N_DIS_MAX + 1];
__device__ int g_off_g[N_GENE_MAX + 1];
__device__ int g_cur_d[N_DIS_MAX];
__device__ int g_cur_g[N_GENE_MAX];
__device__ int g_csr_g2d[E_MAX];   // src gene ids grouped by disease dst
__device__ int g_csr_d2g[E_MAX];   // src disease ids grouped by gene dst
// bf16 hi/lo images of the 8 weight matrices, plain [j][k] row-major
__device__ __align__(16) __nv_bfloat16 g_wimg[16][DIM * DIM];

// ---------------------------------------------------------------------------
__device__ __forceinline__ uint32_t smem_u32(const void* p) {
    uint32_t a;
    asm("{ .reg .u64 t; cvta.to.shared.u64 t, %1; cvt.u32.u64 %0, t; }" : "=r"(a) : "l"(p));
    return a;
}

#define LDMX4(r, addr)                                                         \
    asm volatile("ldmatrix.sync.aligned.m8n8.x4.shared.b16 {%0,%1,%2,%3}, [%4];" \
                 : "=r"((r)[0]), "=r"((r)[1]), "=r"((r)[2]), "=r"((r)[3])      \
                 : "r"(addr))

#define MMA16816(d, a, b0, b1)                                                 \
    asm volatile("mma.sync.aligned.m16n8k16.row.col.f32.bf16.bf16.f32 "        \
                 "{%0,%1,%2,%3}, {%4,%5,%6,%7}, {%8,%9}, {%0,%1,%2,%3};"       \
                 : "+f"((d)[0]), "+f"((d)[1]), "+f"((d)[2]), "+f"((d)[3])      \
                 : "r"((a)[0]), "r"((a)[1]), "r"((a)[2]), "r"((a)[3]),         \
                   "r"(b0), "r"(b1))

// ---------------------------------------------------------------------------
// CSR build (once; graph identical across layers)
// ---------------------------------------------------------------------------
__global__ void zero_int_kernel(int* __restrict__ p, int n) {
    int i = blockIdx.x * blockDim.x + threadIdx.x;
    if (i < n) p[i] = 0;
}

__global__ void count_kernel(const int* __restrict__ dst, int* __restrict__ cnt, int E) {
    int e = blockIdx.x * blockDim.x + threadIdx.x;
    if (e < E) atomicAdd(&cnt[dst[e]], 1);
}

// single-block hierarchical exclusive scan: off[0..n], cursor[i] = off[i]
__global__ void __launch_bounds__(1024)
scan_kernel(const int* __restrict__ cnt, int* __restrict__ off,
            int* __restrict__ cursor, int n) {
    __shared__ int wsum[32];
    __shared__ int carry_s;
    const int t = threadIdx.x, lane = t & 31, wid = t >> 5;
    if (t == 0) { carry_s = 0; off[0] = 0; }
    __syncthreads();
    for (int base = 0; base < n; base += 1024) {
        int i = base + t;
        int v = (i < n) ? cnt[i] : 0;
        int x = v;
#pragma unroll
        for (int o = 1; o < 32; o <<= 1) {
            int y = __shfl_up_sync(0xffffffffu, x, o);
            if (lane >= o) x += y;
        }
        if (lane == 31) wsum[wid] = x;
        __syncthreads();
        if (wid == 0) {
            int s = wsum[lane];
#pragma unroll
            for (int o = 1; o < 32; o <<= 1) {
                int y = __shfl_up_sync(0xffffffffu, s, o);
                if (lane >= o) s += y;
            }
            wsum[lane] = s;
        }
        __syncthreads();
        int incl = x + (wid > 0 ? wsum[wid - 1] : 0) + carry_s;
        if (i < n) { off[i + 1] = incl; cursor[i] = incl - v; }
        __syncthreads();
        if (t == 1023) carry_s = incl;
        __syncthreads();
    }
}

__global__ void fill_kernel(const int* __restrict__ src, const int* __restrict__ dst,
                            int* __restrict__ cursor, int* __restrict__ csr, int E) {
    int e = blockIdx.x * blockDim.x + threadIdx.x;
    if (e < E) {
        int p = atomicAdd(&cursor[dst[e]], 1);
        csr[p] = src[e];
    }
}

// ---------------------------------------------------------------------------
// pull aggregation: warp per dst node, writes the MEAN directly.
// ---------------------------------------------------------------------------
__global__ void __launch_bounds__(256)
pull_kernel(const float* __restrict__ xsrc, const int* __restrict__ csr,
            const int* __restrict__ off, float* __restrict__ agg, int n) {
    const int w = (blockIdx.x * blockDim.x + threadIdx.x) >> 5;
    const int lane = threadIdx.x & 31;
    if (w >= n) return;
    const int start = off[w], end = off[w + 1];
    const float4* __restrict__ base = (const float4*)xsrc;
    float4 acc = make_float4(0.f, 0.f, 0.f, 0.f);
    int e = start;
    for (; e + 4 <= end; e += 4) {
        int s0 = csr[e], s1 = csr[e + 1], s2 = csr[e + 2], s3 = csr[e + 3];
        float4 a = base[(size_t)s0 * 32 + lane];
        float4 b = base[(size_t)s1 * 32 + lane];
        float4 c = base[(size_t)s2 * 32 + lane];
        float4 d = base[(size_t)s3 * 32 + lane];
        acc.x += a.x + b.x + c.x + d.x;
        acc.y += a.y + b.y + c.y + d.y;
        acc.z += a.z + b.z + c.z + d.z;
        acc.w += a.w + b.w + c.w + d.w;
    }
    for (; e < end; e++) {
        float4 a = base[(size_t)csr[e] * 32 + lane];
        acc.x += a.x; acc.y += a.y; acc.z += a.z; acc.w += a.w;
    }
    float inv = 1.0f / fmaxf((float)(end - start), 1.0f);
    acc.x *= inv; acc.y *= inv; acc.z *= inv; acc.w *= inv;
    ((float4*)agg)[(size_t)w * 32 + lane] = acc;
}

// bf16 hi/lo images of all 8 weight matrices (plain row-major)
__global__ void prep_w_kernel(const float* __restrict__ Wl, const float* __restrict__ Wr) {
    int mat = blockIdx.x;            // 0..7 = lt*2 + which
    int lt = mat >> 1, which = mat & 1;
    const float* W = (which ? Wr : Wl) + (size_t)lt * DIM * DIM;
    __nv_bfloat16* ih = g_wimg[mat * 2 + 0];
    __nv_bfloat16* il = g_wimg[mat * 2 + 1];
    for (int i = threadIdx.x; i < DIM * DIM; i += blockDim.x) {
        float w = W[i];
        __nv_bfloat16 h = __float2bfloat16(w);
        ih[i] = h;
        il[i] = __float2bfloat16(w - __bfloat162float(h));
    }
}

// ---------------------------------------------------------------------------
// update: 128 nodes x 128 outputs per CTA, 8 warps (4x2), warp tile 32x64.
// D = zh@Wh^T + zl@Wh^T + zh@Wl^T  (phase0 = mean-agg/Wl, phase1 = x/Wr)
// then +bias, relu?, row-L2norm, x += h.
// ---------------------------------------------------------------------------
#define ZSTRIDE 136
#define TILE_B  (128 * ZSTRIDE * 2)
#define OFF_BIAS 0
#define OFF_ZH   1024
#define OFF_ZL   (OFF_ZH + TILE_B)
#define OFF_WH   (OFF_ZL + TILE_B)
#define OFF_WL   (OFF_WH + TILE_B)
#define SMEM_TOT (OFF_WL + TILE_B)
#define HSTRIDE  132

__global__ void __launch_bounds__(256)
update_kernel(const float* __restrict__ agg,
              float* __restrict__ x,
              const __nv_bfloat16* __restrict__ wl_hi, const __nv_bfloat16* __restrict__ wl_lo,
              const __nv_bfloat16* __restrict__ wr_hi, const __nv_bfloat16* __restrict__ wr_lo,
              const float* __restrict__ bias, int n, int do_relu) {
    extern __shared__ __align__(16) unsigned char smem[];
    const uint32_t sbase = smem_u32(smem);
    const int t    = threadIdx.x;
    const int wid  = t >> 5;
    const int lane = t & 31;
    const int wm   = wid >> 1;
    const int wn   = wid & 1;
    const int r0   = wm * 32;
    const int tile = blockIdx.x * 128;

    float* sbias = (float*)(smem + OFF_BIAS);
    if (t < 128) sbias[t] = bias[t];

    const uint32_t aoff =
        ((uint32_t)((r0 + ((lane >> 3) & 1) * 8 + (lane & 7)) * ZSTRIDE +
                    ((lane >> 4) & 1) * 8)) * 2;
    const uint32_t boff =
        ((uint32_t)((wn * 64 + ((lane >> 4) & 1) * 8 + (lane & 7)) * ZSTRIDE +
                    ((lane >> 3) & 1) * 8)) * 2;

    float acc[2][8][4];
#pragma unroll
    for (int f = 0; f < 2; f++)
#pragma unroll
        for (int j = 0; j < 8; j++)
#pragma unroll
            for (int c = 0; c < 4; c++) acc[f][j][c] = 0.0f;

    for (int phase = 0; phase < 2; phase++) {
        {
            const int k = t & 127;
            __nv_bfloat16* zh = (__nv_bfloat16*)(smem + OFF_ZH);
            __nv_bfloat16* zl = (__nv_bfloat16*)(smem + OFF_ZL);
            const float* zsrc = (phase == 0) ? agg : x;
            for (int row = (t >> 7); row < 128; row += 2) {
                int ng = tile + row;
                float v = (ng < n) ? zsrc[(size_t)ng * DIM + k] : 0.0f;
                __nv_bfloat16 h = __float2bfloat16(v);
                zh[row * ZSTRIDE + k] = h;
                zl[row * ZSTRIDE + k] = __float2bfloat16(v - __bfloat162float(h));
            }
        }
        {
            const uint4* gh = (const uint4*)(phase == 0 ? wl_hi : wr_hi);
            const uint4* gl = (const uint4*)(phase == 0 ? wl_lo : wr_lo);
            for (int i = t; i < 2048; i += 256) {
                int j = i >> 4, kc = i & 15;
                uint32_t off = ((uint32_t)(j * ZSTRIDE + kc * 8)) * 2;
                *(uint4*)(smem + OFF_WH + off) = gh[i];
                *(uint4*)(smem + OFF_WL + off) = gl[i];
            }
        }
        __syncthreads();

        const uint32_t zh_a = sbase + OFF_ZH + aoff;
        const uint32_t wh_b = sbase + OFF_WH + boff;

#pragma unroll
        for (int ks = 0; ks < 8; ks++) {
            uint32_t azh[2][4], azl[2][4], bh[4][4], bl[4][4];
#pragma unroll
            for (int f = 0; f < 2; f++) {
                uint32_t a = zh_a + ks * 32 + f * (16 * ZSTRIDE * 2);
                LDMX4(azh[f], a);
                LDMX4(azl[f], a + TILE_B);
            }
#pragma unroll
            for (int q = 0; q < 4; q++) {
                uint32_t a = wh_b + ks * 32 + q * (16 * ZSTRIDE * 2);
                LDMX4(bh[q], a);
                LDMX4(bl[q], a + TILE_B);
            }
#pragma unroll
            for (int f = 0; f < 2; f++)
#pragma unroll
                for (int j = 0; j < 8; j++) {
                    const int q = j >> 1, s = (j & 1) * 2;
                    MMA16816(acc[f][j], azh[f], bh[q][s], bh[q][s + 1]);
                    MMA16816(acc[f][j], azl[f], bh[q][s], bh[q][s + 1]);
                    MMA16816(acc[f][j], azh[f], bl[q][s], bl[q][s + 1]);
                }
        }
        __syncthreads();
    }

    float* sh = (float*)(smem + OFF_ZH);
#pragma unroll
    for (int f = 0; f < 2; f++) {
        int row = r0 + f * 16 + (lane >> 2);
        int col = wn * 64 + (lane & 3) * 2;
#pragma unroll
        for (int j = 0; j < 8; j++) {
            int c = col + j * 8;
            sh[row * HSTRIDE + c]           = acc[f][j][0];
            sh[row * HSTRIDE + c + 1]       = acc[f][j][1];
            sh[(row + 8) * HSTRIDE + c]     = acc[f][j][2];
            sh[(row + 8) * HSTRIDE + c + 1] = acc[f][j][3];
        }
    }
    __syncthreads();

    {
        const int row  = t >> 1;
        const int half = t & 1;
        const int c0   = half * 64;
        float ssq = 0.0f;
        float h[64];
#pragma unroll
        for (int c = 0; c < 64; c++) {
            float v = sh[row * HSTRIDE + c0 + c] + sbias[c0 + c];
            if (do_relu) v = fmaxf(v, 0.0f);
            h[c] = v;
            ssq += v * v;
        }
        ssq += __shfl_xor_sync(0xffffffffu, ssq, 1);
        float sc = 1.0f / fmaxf(sqrtf(ssq), 1e-12f);

        int node = tile + row;
        if (node < n) {
            float4* xr = (float4*)(x + (size_t)node * DIM + c0);
#pragma unroll
            for (int q = 0; q < 16; q++) {
                float4 o = xr[q];
                o.x += h[q * 4 + 0] * sc;
                o.y += h[q * 4 + 1] * sc;
                o.z += h[q * 4 + 2] * sc;
                o.w += h[q * 4 + 3] * sc;
                xr[q] = o;
            }
        }
    }
}

// ---------------------------------------------------------------------------
extern "C" void kernel_launch(void* const* d_in, const int* in_sizes, int n_in,
                              void* d_out, int out_size) {
    const float* x_gene  = (const float*)d_in[0];
    const float* x_dis   = (const float*)d_in[1];
    const float* Wl      = (const float*)d_in[2];
    const float* Wr      = (const float*)d_in[3];
    const float* b       = (const float*)d_in[4];
    const int*   src_g2d = (const int*)d_in[5];
    const int*   dst_g2d = (const int*)d_in[6];
    const int*   src_d2g = (const int*)d_in[7];
    const int*   dst_d2g = (const int*)d_in[8];

    const int n_gene = in_sizes[0] / DIM;
    const int n_dis  = in_sizes[1] / DIM;
    const int E1 = in_sizes[5];
    const int E2 = in_sizes[7];

    float *agg_d, *agg_g;
    int *cnt_d, *cnt_g, *off_d, *off_g, *cur_d, *cur_g, *csr_g2d, *csr_d2g;
    __nv_bfloat16* wimg;
    cudaGetSymbolAddress((void**)&agg_d, g_agg_d);
    cudaGetSymbolAddress((void**)&agg_g, g_agg_g);
    cudaGetSymbolAddress((void**)&cnt_d, g_cnt_d);
    cudaGetSymbolAddress((void**)&cnt_g, g_cnt_g);
    cudaGetSymbolAddress((void**)&off_d, g_off_d);
    cudaGetSymbolAddress((void**)&off_g, g_off_g);
    cudaGetSymbolAddress((void**)&cur_d, g_cur_d);
    cudaGetSymbolAddress((void**)&cur_g, g_cur_g);
    cudaGetSymbolAddress((void**)&csr_g2d, g_csr_g2d);
    cudaGetSymbolAddress((void**)&csr_d2g, g_csr_d2g);
    cudaGetSymbolAddress((void**)&wimg, g_wimg);

    float* xg = (float*)d_out;
    float* xd = xg + (size_t)n_gene * DIM;

    cudaMemcpyAsync(xg, x_gene, (size_t)n_gene * DIM * sizeof(float),
                    cudaMemcpyDeviceToDevice, 0);
    cudaMemcpyAsync(xd, x_dis, (size_t)n_dis * DIM * sizeof(float),
                    cudaMemcpyDeviceToDevice, 0);

    prep_w_kernel<<<8, 256>>>(Wl, Wr);

    // ---- CSR build (once; graph static across layers) ----
    zero_int_kernel<<<(n_dis + 255) / 256, 256>>>(cnt_d, n_dis);
    zero_int_kernel<<<(n_gene + 255) / 256, 256>>>(cnt_g, n_gene);
    count_kernel<<<(E1 + 255) / 256, 256>>>(dst_g2d, cnt_d, E1);
    count_kernel<<<(E2 + 255) / 256, 256>>>(dst_d2g, cnt_g, E2);
    scan_kernel<<<1, 1024>>>(cnt_d, off_d, cur_d, n_dis);
    scan_kernel<<<1, 1024>>>(cnt_g, off_g, cur_g, n_gene);
    fill_kernel<<<(E1 + 255) / 256, 256>>>(src_g2d, dst_g2d, cur_d, csr_g2d, E1);
    fill_kernel<<<(E2 + 255) / 256, 256>>>(src_d2g, dst_d2g, cur_g, csr_d2g, E2);

    cudaFuncSetAttribute(update_kernel,
                         cudaFuncAttributeMaxDynamicSharedMemorySize, SMEM_TOT);

    for (int i = 0; i < 2; i++) {
        // both pulls read the PRE-layer state; updates run after both
        pull_kernel<<<(n_dis + 7) / 8, 256>>>(xg, csr_g2d, off_d, agg_d, n_dis);
        pull_kernel<<<(n_gene + 7) / 8, 256>>>(xd, csr_d2g, off_g, agg_g, n_gene);

        const __nv_bfloat16* p = wimg;
        const __nv_bfloat16* wl_hi_d = p + (size_t)(((i * 2 + 0) * 2 + 0) * 2 + 0) * DIM * DIM;
        const __nv_bfloat16* wl_lo_d = p + (size_t)(((i * 2 + 0) * 2 + 0) * 2 + 1) * DIM * DIM;
        const __nv_bfloat16* wr_hi_d = p + (size_t)(((i * 2 + 0) * 2 + 1) * 2 + 0) * DIM * DIM;
        const __nv_bfloat16* wr_lo_d = p + (size_t)(((i * 2 + 0) * 2 + 1) * 2 + 1) * DIM * DIM;
        const __nv_bfloat16* wl_hi_g = p + (size_t)(((i * 2 + 1) * 2 + 0) * 2 + 0) * DIM * DIM;
        const __nv_bfloat16* wl_lo_g = p + (size_t)(((i * 2 + 1) * 2 + 0) * 2 + 1) * DIM * DIM;
        const __nv_bfloat16* wr_hi_g = p + (size_t)(((i * 2 + 1) * 2 + 1) * 2 + 0) * DIM * DIM;
        const __nv_bfloat16* wr_lo_g = p + (size_t)(((i * 2 + 1) * 2 + 1) * 2 + 1) * DIM * DIM;
        const float* b_d = b + (size_t)(i * 2 + 0) * DIM;
        const float* b_g = b + (size_t)(i * 2 + 1) * DIM;

        update_kernel<<<(n_dis + 127) / 128, 256, SMEM_TOT>>>(
            agg_d, xd, wl_hi_d, wl_lo_d, wr_hi_d, wr_lo_d, b_d, n_dis, i == 0 ? 1 : 0);
        update_kernel<<<(n_gene + 127) / 128, 256, SMEM_TOT>>>(
            agg_g, xg, wl_hi_g, wl_lo_g, wr_hi_g, wr_lo_g, b_g, n_gene, i == 0 ? 1 : 0);
    }
}

// round 5
// speedup vs baseline: 2.0889x; 1.1478x over previous
#include <cuda_runtime.h>
#include <cuda_bf16.h>
#include <cstdint>
#include <cstddef>

// ---------------------------------------------------------------------------
// multilayer_message_passing: 2-layer hetero GraphSAGE.
// R5: fused dual-type launches (pull, update, CSR build), no memcpy (layer-0
//     reads inputs directly), 2-block parallel scan, 8-deep pull unroll.
// ---------------------------------------------------------------------------

#define N_GENE_MAX 100000
#define N_DIS_MAX   50000
#define DIM 128
#define E_MAX 800000

__device__ float g_agg_d[(size_t)N_DIS_MAX  * DIM];
__device__ float g_agg_g[(size_t)N_GENE_MAX * DIM];
__device__ int g_cnt_d[N_DIS_MAX];
__device__ int g_cnt_g[N_GENE_MAX];
__device__ int g_off_d[N_DIS_MAX + 1];
__device__ int g_off_g[N_GENE_MAX + 1];
__device__ int g_cur_d[N_DIS_MAX];
__device__ int g_cur_g[N_GENE_MAX];
__device__ int g_csr_g2d[E_MAX];   // src gene ids grouped by disease dst
__device__ int g_csr_d2g[E_MAX];   // src disease ids grouped by gene dst
// bf16 hi/lo images of the 8 weight matrices, [ (lt*2+which)*2+half ][128*128]
__device__ __align__(16) __nv_bfloat16 g_wimg[16][DIM * DIM];

// ---------------------------------------------------------------------------
__device__ __forceinline__ uint32_t smem_u32(const void* p) {
    uint32_t a;
    asm("{ .reg .u64 t; cvta.to.shared.u64 t, %1; cvt.u32.u64 %0, t; }" : "=r"(a) : "l"(p));
    return a;
}

#define LDMX4(r, addr)                                                         \
    asm volatile("ldmatrix.sync.aligned.m8n8.x4.shared.b16 {%0,%1,%2,%3}, [%4];" \
                 : "=r"((r)[0]), "=r"((r)[1]), "=r"((r)[2]), "=r"((r)[3])      \
                 : "r"(addr))

#define MMA16816(d, a, b0, b1)                                                 \
    asm volatile("mma.sync.aligned.m16n8k16.row.col.f32.bf16.bf16.f32 "        \
                 "{%0,%1,%2,%3}, {%4,%5,%6,%7}, {%8,%9}, {%0,%1,%2,%3};"       \
                 : "+f"((d)[0]), "+f"((d)[1]), "+f"((d)[2]), "+f"((d)[3])      \
                 : "r"((a)[0]), "r"((a)[1]), "r"((a)[2]), "r"((a)[3]),         \
                   "r"(b0), "r"(b1))

// ---------------------------------------------------------------------------
// CSR build (fused over both edge types)
// ---------------------------------------------------------------------------
__global__ void zero2_kernel(int* __restrict__ a, int na, int* __restrict__ b, int nb) {
    int i = blockIdx.x * blockDim.x + threadIdx.x;
    if (i < na) a[i] = 0;
    if (i < nb) b[i] = 0;
}

__global__ void count2_kernel(const int* __restrict__ dst1, int* __restrict__ cnt1, int E1,
                              const int* __restrict__ dst2, int* __restrict__ cnt2, int E2) {
    int e = blockIdx.x * blockDim.x + threadIdx.x;
    if (e < E1) atomicAdd(&cnt1[dst1[e]], 1);
    else if (e < E1 + E2) atomicAdd(&cnt2[dst2[e - E1]], 1);
}

// block 0 scans (cnt1 -> off1,cur1), block 1 scans (cnt2 -> off2,cur2)
__global__ void __launch_bounds__(1024)
scan2_kernel(const int* __restrict__ cnt1, int* __restrict__ off1, int* __restrict__ cur1, int n1,
             const int* __restrict__ cnt2, int* __restrict__ off2, int* __restrict__ cur2, int n2) {
    const int* cnt = blockIdx.x ? cnt2 : cnt1;
    int* off = blockIdx.x ? off2 : off1;
    int* cursor = blockIdx.x ? cur2 : cur1;
    int n = blockIdx.x ? n2 : n1;

    __shared__ int wsum[32];
    __shared__ int carry_s;
    const int t = threadIdx.x, lane = t & 31, wid = t >> 5;
    if (t == 0) { carry_s = 0; off[0] = 0; }
    __syncthreads();
    for (int base = 0; base < n; base += 1024) {
        int i = base + t;
        int v = (i < n) ? cnt[i] : 0;
        int x = v;
#pragma unroll
        for (int o = 1; o < 32; o <<= 1) {
            int y = __shfl_up_sync(0xffffffffu, x, o);
            if (lane >= o) x += y;
        }
        if (lane == 31) wsum[wid] = x;
        __syncthreads();
        if (wid == 0) {
            int s = wsum[lane];
#pragma unroll
            for (int o = 1; o < 32; o <<= 1) {
                int y = __shfl_up_sync(0xffffffffu, s, o);
                if (lane >= o) s += y;
            }
            wsum[lane] = s;
        }
        __syncthreads();
        int incl = x + (wid > 0 ? wsum[wid - 1] : 0) + carry_s;
        if (i < n) { off[i + 1] = incl; cursor[i] = incl - v; }
        __syncthreads();
        if (t == 1023) carry_s = incl;
        __syncthreads();
    }
}

__global__ void fill2_kernel(const int* __restrict__ src1, const int* __restrict__ dst1,
                             int* __restrict__ cur1, int* __restrict__ csr1, int E1,
                             const int* __restrict__ src2, const int* __restrict__ dst2,
                             int* __restrict__ cur2, int* __restrict__ csr2, int E2) {
    int e = blockIdx.x * blockDim.x + threadIdx.x;
    if (e < E1) {
        int p = atomicAdd(&cur1[dst1[e]], 1);
        csr1[p] = src1[e];
    } else if (e < E1 + E2) {
        int i = e - E1;
        int p = atomicAdd(&cur2[dst2[i]], 1);
        csr2[p] = src2[i];
    }
}

// ---------------------------------------------------------------------------
// fused pull aggregation: warp per dst node (both types in one grid),
// writes the MEAN directly. 8-deep unroll, dual accumulator chains.
// ---------------------------------------------------------------------------
__global__ void __launch_bounds__(256)
pull_fused_kernel(const float* __restrict__ xg_src, const float* __restrict__ xd_src,
                  float* __restrict__ agg_d, float* __restrict__ agg_g,
                  const int* __restrict__ csr_g2d, const int* __restrict__ off_d,
                  const int* __restrict__ csr_d2g, const int* __restrict__ off_g,
                  int n_dis, int n_gene) {
    const int w = (blockIdx.x * blockDim.x + threadIdx.x) >> 5;
    const int lane = threadIdx.x & 31;
    const float4* __restrict__ base;
    const int* __restrict__ csr;
    const int* __restrict__ off;
    float* aggp;
    int node;
    if (w < n_dis) {
        node = w; base = (const float4*)xg_src; csr = csr_g2d; off = off_d;
        aggp = agg_d;
    } else if (w < n_dis + n_gene) {
        node = w - n_dis; base = (const float4*)xd_src; csr = csr_d2g; off = off_g;
        aggp = agg_g;
    } else return;

    const int start = off[node], end = off[node + 1];
    float4 acc0 = make_float4(0.f, 0.f, 0.f, 0.f);
    float4 acc1 = make_float4(0.f, 0.f, 0.f, 0.f);
    int e = start;
    for (; e + 8 <= end; e += 8) {
        int s0 = csr[e],     s1 = csr[e + 1], s2 = csr[e + 2], s3 = csr[e + 3];
        int s4 = csr[e + 4], s5 = csr[e + 5], s6 = csr[e + 6], s7 = csr[e + 7];
        float4 a = base[(size_t)s0 * 32 + lane];
        float4 b = base[(size_t)s1 * 32 + lane];
        float4 c = base[(size_t)s2 * 32 + lane];
        float4 d = base[(size_t)s3 * 32 + lane];
        float4 p = base[(size_t)s4 * 32 + lane];
        float4 q = base[(size_t)s5 * 32 + lane];
        float4 r = base[(size_t)s6 * 32 + lane];
        float4 s = base[(size_t)s7 * 32 + lane];
        acc0.x += a.x + b.x; acc0.y += a.y + b.y; acc0.z += a.z + b.z; acc0.w += a.w + b.w;
        acc1.x += c.x + d.x; acc1.y += c.y + d.y; acc1.z += c.z + d.z; acc1.w += c.w + d.w;
        acc0.x += p.x + q.x; acc0.y += p.y + q.y; acc0.z += p.z + q.z; acc0.w += p.w + q.w;
        acc1.x += r.x + s.x; acc1.y += r.y + s.y; acc1.z += r.z + s.z; acc1.w += r.w + s.w;
    }
    for (; e + 2 <= end; e += 2) {
        float4 a = base[(size_t)csr[e] * 32 + lane];
        float4 b = base[(size_t)csr[e + 1] * 32 + lane];
        acc0.x += a.x; acc0.y += a.y; acc0.z += a.z; acc0.w += a.w;
        acc1.x += b.x; acc1.y += b.y; acc1.z += b.z; acc1.w += b.w;
    }
    if (e < end) {
        float4 a = base[(size_t)csr[e] * 32 + lane];
        acc0.x += a.x; acc0.y += a.y; acc0.z += a.z; acc0.w += a.w;
    }
    float inv = 1.0f / fmaxf((float)(end - start), 1.0f);
    float4 o;
    o.x = (acc0.x + acc1.x) * inv;
    o.y = (acc0.y + acc1.y) * inv;
    o.z = (acc0.z + acc1.z) * inv;
    o.w = (acc0.w + acc1.w) * inv;
    ((float4*)aggp)[(size_t)node * 32 + lane] = o;
}

// bf16 hi/lo images of all 8 weight matrices (plain row-major)
__global__ void prep_w_kernel(const float* __restrict__ Wl, const float* __restrict__ Wr) {
    int mat = blockIdx.x;            // 0..7 = lt*2 + which
    int lt = mat >> 1, which = mat & 1;
    const float* W = (which ? Wr : Wl) + (size_t)lt * DIM * DIM;
    __nv_bfloat16* ih = g_wimg[mat * 2 + 0];
    __nv_bfloat16* il = g_wimg[mat * 2 + 1];
    for (int i = threadIdx.x; i < DIM * DIM; i += blockDim.x) {
        float w = W[i];
        __nv_bfloat16 h = __float2bfloat16(w);
        ih[i] = h;
        il[i] = __float2bfloat16(w - __bfloat162float(h));
    }
}

// ---------------------------------------------------------------------------
// fused update: blocks [0,nbd) -> disease, [nbd,nbd+nbg) -> gene.
// per CTA: 128 nodes x 128 outs, 8 warps (4x2), warp tile 32x64.
// D = zh@Wh^T + zl@Wh^T + zh@Wl^T (phase0 = mean-agg/Wl, phase1 = xin/Wr)
// epilogue: +bias, relu?, row-L2norm, xout = xin + h.
// ---------------------------------------------------------------------------
#define ZSTRIDE 136
#define TILE_B  (128 * ZSTRIDE * 2)
#define OFF_BIAS 0
#define OFF_ZH   1024
#define OFF_ZL   (OFF_ZH + TILE_B)
#define OFF_WH   (OFF_ZL + TILE_B)
#define OFF_WL   (OFF_WH + TILE_B)
#define SMEM_TOT (OFF_WL + TILE_B)
#define HSTRIDE  132

__global__ void __launch_bounds__(256)
update_fused_kernel(const float* __restrict__ agg_d, const float* __restrict__ xin_d,
                    float* __restrict__ xout_d, int n_d,
                    const float* __restrict__ agg_g, const float* __restrict__ xin_g,
                    float* __restrict__ xout_g, int n_g,
                    const __nv_bfloat16* __restrict__ wimg, const float* __restrict__ bias_base,
                    int layer, int nbd, int do_relu) {
    extern __shared__ __align__(16) unsigned char smem[];
    const uint32_t sbase = smem_u32(smem);
    const int t    = threadIdx.x;
    const int wid  = t >> 5;
    const int lane = t & 31;
    const int wm   = wid >> 1;
    const int wn   = wid & 1;
    const int r0   = wm * 32;

    // per-type selection
    const int is_g = (blockIdx.x >= nbd) ? 1 : 0;
    const int tile = (is_g ? (blockIdx.x - nbd) : blockIdx.x) * 128;
    const float* agg  = is_g ? agg_g : agg_d;
    const float* xin  = is_g ? xin_g : xin_d;
    float*       xout = is_g ? xout_g : xout_d;
    const int n = is_g ? n_g : n_d;
    const int lt = layer * 2 + is_g;
    const __nv_bfloat16* wl_hi = wimg + (size_t)(lt * 4 + 0) * DIM * DIM;
    const __nv_bfloat16* wl_lo = wimg + (size_t)(lt * 4 + 1) * DIM * DIM;
    const __nv_bfloat16* wr_hi = wimg + (size_t)(lt * 4 + 2) * DIM * DIM;
    const __nv_bfloat16* wr_lo = wimg + (size_t)(lt * 4 + 3) * DIM * DIM;
    const float* bias = bias_base + (size_t)lt * DIM;

    float* sbias = (float*)(smem + OFF_BIAS);
    if (t < 128) sbias[t] = bias[t];

    const uint32_t aoff =
        ((uint32_t)((r0 + ((lane >> 3) & 1) * 8 + (lane & 7)) * ZSTRIDE +
                    ((lane >> 4) & 1) * 8)) * 2;
    const uint32_t boff =
        ((uint32_t)((wn * 64 + ((lane >> 4) & 1) * 8 + (lane & 7)) * ZSTRIDE +
                    ((lane >> 3) & 1) * 8)) * 2;

    float acc[2][8][4];
#pragma unroll
    for (int f = 0; f < 2; f++)
#pragma unroll
        for (int j = 0; j < 8; j++)
#pragma unroll
            for (int c = 0; c < 4; c++) acc[f][j][c] = 0.0f;

    for (int phase = 0; phase < 2; phase++) {
        {
            const int k = t & 127;
            __nv_bfloat16* zh = (__nv_bfloat16*)(smem + OFF_ZH);
            __nv_bfloat16* zl = (__nv_bfloat16*)(smem + OFF_ZL);
            const float* zsrc = (phase == 0) ? agg : xin;
            for (int row = (t >> 7); row < 128; row += 2) {
                int ng = tile + row;
                float v = (ng < n) ? zsrc[(size_t)ng * DIM + k] : 0.0f;
                __nv_bfloat16 h = __float2bfloat16(v);
                zh[row * ZSTRIDE + k] = h;
                zl[row * ZSTRIDE + k] = __float2bfloat16(v - __bfloat162float(h));
            }
        }
        {
            const uint4* gh = (const uint4*)(phase == 0 ? wl_hi : wr_hi);
            const uint4* gl = (const uint4*)(phase == 0 ? wl_lo : wr_lo);
            for (int i = t; i < 2048; i += 256) {
                int j = i >> 4, kc = i & 15;
                uint32_t off = ((uint32_t)(j * ZSTRIDE + kc * 8)) * 2;
                *(uint4*)(smem + OFF_WH + off) = gh[i];
                *(uint4*)(smem + OFF_WL + off) = gl[i];
            }
        }
        __syncthreads();

        const uint32_t zh_a = sbase + OFF_ZH + aoff;
        const uint32_t wh_b = sbase + OFF_WH + boff;

#pragma unroll
        for (int ks = 0; ks < 8; ks++) {
            uint32_t azh[2][4], azl[2][4], bh[4][4], bl[4][4];
#pragma unroll
            for (int f = 0; f < 2; f++) {
                uint32_t a = zh_a + ks * 32 + f * (16 * ZSTRIDE * 2);
                LDMX4(azh[f], a);
                LDMX4(azl[f], a + TILE_B);
            }
#pragma unroll
            for (int q = 0; q < 4; q++) {
                uint32_t a = wh_b + ks * 32 + q * (16 * ZSTRIDE * 2);
                LDMX4(bh[q], a);
                LDMX4(bl[q], a + TILE_B);
            }
#pragma unroll
            for (int f = 0; f < 2; f++)
#pragma unroll
                for (int j = 0; j < 8; j++) {
                    const int q = j >> 1, s = (j & 1) * 2;
                    MMA16816(acc[f][j], azh[f], bh[q][s], bh[q][s + 1]);
                    MMA16816(acc[f][j], azl[f], bh[q][s], bh[q][s + 1]);
                    MMA16816(acc[f][j], azh[f], bl[q][s], bl[q][s + 1]);
                }
        }
        __syncthreads();
    }

    float* sh = (float*)(smem + OFF_ZH);
#pragma unroll
    for (int f = 0; f < 2; f++) {
        int row = r0 + f * 16 + (lane >> 2);
        int col = wn * 64 + (lane & 3) * 2;
#pragma unroll
        for (int j = 0; j < 8; j++) {
            int c = col + j * 8;
            sh[row * HSTRIDE + c]           = acc[f][j][0];
            sh[row * HSTRIDE + c + 1]       = acc[f][j][1];
            sh[(row + 8) * HSTRIDE + c]     = acc[f][j][2];
            sh[(row + 8) * HSTRIDE + c + 1] = acc[f][j][3];
        }
    }
    __syncthreads();

    {
        const int row  = t >> 1;
        const int half = t & 1;
        const int c0   = half * 64;
        float ssq = 0.0f;
        float h[64];
#pragma unroll
        for (int c = 0; c < 64; c++) {
            float v = sh[row * HSTRIDE + c0 + c] + sbias[c0 + c];
            if (do_relu) v = fmaxf(v, 0.0f);
            h[c] = v;
            ssq += v * v;
        }
        ssq += __shfl_xor_sync(0xffffffffu, ssq, 1);
        float sc = 1.0f / fmaxf(sqrtf(ssq), 1e-12f);

        int node = tile + row;
        if (node < n) {
            const float4* xi = (const float4*)(xin + (size_t)node * DIM + c0);
            float4* xo = (float4*)(xout + (size_t)node * DIM + c0);
#pragma unroll
            for (int q = 0; q < 16; q++) {
                float4 o = xi[q];
                o.x += h[q * 4 + 0] * sc;
                o.y += h[q * 4 + 1] * sc;
                o.z += h[q * 4 + 2] * sc;
                o.w += h[q * 4 + 3] * sc;
                xo[q] = o;
            }
        }
    }
}

// ---------------------------------------------------------------------------
extern "C" void kernel_launch(void* const* d_in, const int* in_sizes, int n_in,
                              void* d_out, int out_size) {
    const float* x_gene  = (const float*)d_in[0];
    const float* x_dis   = (const float*)d_in[1];
    const float* Wl      = (const float*)d_in[2];
    const float* Wr      = (const float*)d_in[3];
    const float* b       = (const float*)d_in[4];
    const int*   src_g2d = (const int*)d_in[5];
    const int*   dst_g2d = (const int*)d_in[6];
    const int*   src_d2g = (const int*)d_in[7];
    const int*   dst_d2g = (const int*)d_in[8];

    const int n_gene = in_sizes[0] / DIM;
    const int n_dis  = in_sizes[1] / DIM;
    const int E1 = in_sizes[5];
    const int E2 = in_sizes[7];

    float *agg_d, *agg_g;
    int *cnt_d, *cnt_g, *off_d, *off_g, *cur_d, *cur_g, *csr_g2d, *csr_d2g;
    __nv_bfloat16* wimg;
    cudaGetSymbolAddress((void**)&agg_d, g_agg_d);
    cudaGetSymbolAddress((void**)&agg_g, g_agg_g);
    cudaGetSymbolAddress((void**)&cnt_d, g_cnt_d);
    cudaGetSymbolAddress((void**)&cnt_g, g_cnt_g);
    cudaGetSymbolAddress((void**)&off_d, g_off_d);
    cudaGetSymbolAddress((void**)&off_g, g_off_g);
    cudaGetSymbolAddress((void**)&cur_d, g_cur_d);
    cudaGetSymbolAddress((void**)&cur_g, g_cur_g);
    cudaGetSymbolAddress((void**)&csr_g2d, g_csr_g2d);
    cudaGetSymbolAddress((void**)&csr_d2g, g_csr_d2g);
    cudaGetSymbolAddress((void**)&wimg, g_wimg);

    float* xg = (float*)d_out;
    float* xd = xg + (size_t)n_gene * DIM;

    prep_w_kernel<<<8, 256>>>(Wl, Wr);

    // ---- CSR build (once; graph static across layers) ----
    int nz = (n_gene > n_dis ? n_gene : n_dis);
    zero2_kernel<<<(nz + 255) / 256, 256>>>(cnt_d, n_dis, cnt_g, n_gene);
    count2_kernel<<<(E1 + E2 + 255) / 256, 256>>>(dst_g2d, cnt_d, E1, dst_d2g, cnt_g, E2);
    scan2_kernel<<<2, 1024>>>(cnt_d, off_d, cur_d, n_dis, cnt_g, off_g, cur_g, n_gene);
    fill2_kernel<<<(E1 + E2 + 255) / 256, 256>>>(src_g2d, dst_g2d, cur_d, csr_g2d, E1,
                                                 src_d2g, dst_d2g, cur_g, csr_d2g, E2);

    cudaFuncSetAttribute(update_fused_kernel,
                         cudaFuncAttributeMaxDynamicSharedMemorySize, SMEM_TOT);

    const int nbd = (n_dis + 127) / 128;
    const int nbg = (n_gene + 127) / 128;
    const int pull_blocks = ((n_dis + n_gene) * 32 + 255) / 256;

    // ---- layer 0: read inputs directly, write d_out ----
    pull_fused_kernel<<<pull_blocks, 256>>>(x_gene, x_dis, agg_d, agg_g,
                                            csr_g2d, off_d, csr_d2g, off_g,
                                            n_dis, n_gene);
    update_fused_kernel<<<nbd + nbg, 256, SMEM_TOT>>>(
        agg_d, x_dis, xd, n_dis, agg_g, x_gene, xg, n_gene,
        wimg, b, 0, nbd, 1);

    // ---- layer 1: in place on d_out ----
    pull_fused_kernel<<<pull_blocks, 256>>>(xg, xd, agg_d, agg_g,
                                            csr_g2d, off_d, csr_d2g, off_g,
                                            n_dis, n_gene);
    update_fused_kernel<<<nbd + nbg, 256, SMEM_TOT>>>(
        agg_d, xd, xd, n_dis, agg_g, xg, xg, n_gene,
        wimg, b, 1, nbd, 0);
}

// round 6
// speedup vs baseline: 2.2756x; 1.0894x over previous
#include <cuda_runtime.h>
#include <cuda_bf16.h>
#include <cstdint>
#include <cstddef>

// ---------------------------------------------------------------------------
// multilayer_message_passing: 2-layer hetero GraphSAGE.
// R6: multi-block 3-phase CSR scan (replaces 94us 2-block serial scan).
//     Otherwise identical to R5 (fused pulls/updates, no memcpy).
// ---------------------------------------------------------------------------

#define N_GENE_MAX 100000
#define N_DIS_MAX   50000
#define DIM 128
#define E_MAX 800000
#define SCAN_TILE 4096     // items per scan block (1024 thr x 4)

__device__ float g_agg_d[(size_t)N_DIS_MAX  * DIM];
__device__ float g_agg_g[(size_t)N_GENE_MAX * DIM];
__device__ int g_cnt_d[N_DIS_MAX];
__device__ int g_cnt_g[N_GENE_MAX];
__device__ int g_off_d[N_DIS_MAX + 1];
__device__ int g_off_g[N_GENE_MAX + 1];
__device__ int g_cur_d[N_DIS_MAX];
__device__ int g_cur_g[N_GENE_MAX];
__device__ int g_csr_g2d[E_MAX];
__device__ int g_csr_d2g[E_MAX];
__device__ int g_tmp[N_DIS_MAX + N_GENE_MAX];   // local-exclusive scan values
__device__ int g_part[128];                      // per-block partial sums
__device__ __align__(16) __nv_bfloat16 g_wimg[16][DIM * DIM];

// ---------------------------------------------------------------------------
__device__ __forceinline__ uint32_t smem_u32(const void* p) {
    uint32_t a;
    asm("{ .reg .u64 t; cvta.to.shared.u64 t, %1; cvt.u32.u64 %0, t; }" : "=r"(a) : "l"(p));
    return a;
}

#define LDMX4(r, addr)                                                         \
    asm volatile("ldmatrix.sync.aligned.m8n8.x4.shared.b16 {%0,%1,%2,%3}, [%4];" \
                 : "=r"((r)[0]), "=r"((r)[1]), "=r"((r)[2]), "=r"((r)[3])      \
                 : "r"(addr))

#define MMA16816(d, a, b0, b1)                                                 \
    asm volatile("mma.sync.aligned.m16n8k16.row.col.f32.bf16.bf16.f32 "        \
                 "{%0,%1,%2,%3}, {%4,%5,%6,%7}, {%8,%9}, {%0,%1,%2,%3};"       \
                 : "+f"((d)[0]), "+f"((d)[1]), "+f"((d)[2]), "+f"((d)[3])      \
                 : "r"((a)[0]), "r"((a)[1]), "r"((a)[2]), "r"((a)[3]),         \
                   "r"(b0), "r"(b1))

// ---------------------------------------------------------------------------
// CSR build
// ---------------------------------------------------------------------------
__global__ void zero2_kernel(int* __restrict__ a, int na, int* __restrict__ b, int nb) {
    int i = blockIdx.x * blockDim.x + threadIdx.x;
    if (i < na) a[i] = 0;
    if (i < nb) b[i] = 0;
}

__global__ void count2_kernel(const int* __restrict__ dst1, int* __restrict__ cnt1, int E1,
                              const int* __restrict__ dst2, int* __restrict__ cnt2, int E2) {
    int e = blockIdx.x * blockDim.x + threadIdx.x;
    if (e < E1) atomicAdd(&cnt1[dst1[e]], 1);
    else if (e < E1 + E2) atomicAdd(&cnt2[dst2[e - E1]], 1);
}

// phase 1: per-block local exclusive scan over the concatenated count domain.
__global__ void __launch_bounds__(1024)
scan_p1_kernel(const int* __restrict__ cnt_d, int n_dis,
               const int* __restrict__ cnt_g, int n_gene,
               int* __restrict__ tmp, int* __restrict__ part) {
    __shared__ int wsum[32];
    const int n_tot = n_dis + n_gene;
    const int t = threadIdx.x, lane = t & 31, wid = t >> 5;
    const int base = blockIdx.x * SCAN_TILE + t * 4;

    int v[4];
#pragma unroll
    for (int j = 0; j < 4; j++) {
        int i = base + j;
        v[j] = (i < n_tot) ? (i < n_dis ? cnt_d[i] : cnt_g[i - n_dis]) : 0;
    }
    int tsum = v[0] + v[1] + v[2] + v[3];
    int x = tsum;
#pragma unroll
    for (int o = 1; o < 32; o <<= 1) {
        int y = __shfl_up_sync(0xffffffffu, x, o);
        if (lane >= o) x += y;
    }
    if (lane == 31) wsum[wid] = x;
    __syncthreads();
    if (wid == 0) {
        int s = wsum[lane];
#pragma unroll
        for (int o = 1; o < 32; o <<= 1) {
            int y = __shfl_up_sync(0xffffffffu, s, o);
            if (lane >= o) s += y;
        }
        wsum[lane] = s;
    }
    __syncthreads();
    int ex = (x - tsum) + (wid > 0 ? wsum[wid - 1] : 0);
#pragma unroll
    for (int j = 0; j < 4; j++) {
        int i = base + j;
        if (i < n_tot) tmp[i] = ex;
        ex += v[j];
    }
    if (t == 1023) part[blockIdx.x] = wsum[31];
}

// phase 2: exclusive scan of <=128 block partials (single small block)
__global__ void __launch_bounds__(128)
scan_p2_kernel(int* __restrict__ part, int nb) {
    __shared__ int wsum[4];
    const int t = threadIdx.x, lane = t & 31, wid = t >> 5;
    int v = (t < nb) ? part[t] : 0;
    int x = v;
#pragma unroll
    for (int o = 1; o < 32; o <<= 1) {
        int y = __shfl_up_sync(0xffffffffu, x, o);
        if (lane >= o) x += y;
    }
    if (lane == 31) wsum[wid] = x;
    __syncthreads();
    if (t == 0) {
        int c = 0;
#pragma unroll
        for (int q = 0; q < 4; q++) { int w = wsum[q]; wsum[q] = c; c += w; }
    }
    __syncthreads();
    if (t < nb) part[t] = (x - v) + wsum[wid];
}

// phase 3: combine, split back into off/cur, set sentinel offsets
__global__ void scan_p3_kernel(const int* __restrict__ tmp, const int* __restrict__ part,
                               int* __restrict__ off_d, int* __restrict__ cur_d, int n_dis,
                               int* __restrict__ off_g, int* __restrict__ cur_g, int n_gene,
                               int E1, int E2) {
    int i = blockIdx.x * blockDim.x + threadIdx.x;
    int n_tot = n_dis + n_gene;
    if (i < n_tot) {
        int ex = tmp[i] + part[i >> 12];   // SCAN_TILE == 4096
        if (i < n_dis) { off_d[i] = ex; cur_d[i] = ex; }
        else { int k = i - n_dis; int e = ex - E1; off_g[k] = e; cur_g[k] = e; }
    }
    if (i == 0) { off_d[n_dis] = E1; off_g[n_gene] = E2; }
}

__global__ void fill2_kernel(const int* __restrict__ src1, const int* __restrict__ dst1,
                             int* __restrict__ cur1, int* __restrict__ csr1, int E1,
                             const int* __restrict__ src2, const int* __restrict__ dst2,
                             int* __restrict__ cur2, int* __restrict__ csr2, int E2) {
    int e = blockIdx.x * blockDim.x + threadIdx.x;
    if (e < E1) {
        int p = atomicAdd(&cur1[dst1[e]], 1);
        csr1[p] = src1[e];
    } else if (e < E1 + E2) {
        int i = e - E1;
        int p = atomicAdd(&cur2[dst2[i]], 1);
        csr2[p] = src2[i];
    }
}

// ---------------------------------------------------------------------------
// fused pull aggregation: warp per dst node, writes the MEAN directly.
// ---------------------------------------------------------------------------
__global__ void __launch_bounds__(256)
pull_fused_kernel(const float* __restrict__ xg_src, const float* __restrict__ xd_src,
                  float* __restrict__ agg_d, float* __restrict__ agg_g,
                  const int* __restrict__ csr_g2d, const int* __restrict__ off_d,
                  const int* __restrict__ csr_d2g, const int* __restrict__ off_g,
                  int n_dis, int n_gene) {
    const int w = (blockIdx.x * blockDim.x + threadIdx.x) >> 5;
    const int lane = threadIdx.x & 31;
    const float4* __restrict__ base;
    const int* __restrict__ csr;
    const int* __restrict__ off;
    float* aggp;
    int node;
    if (w < n_dis) {
        node = w; base = (const float4*)xg_src; csr = csr_g2d; off = off_d;
        aggp = agg_d;
    } else if (w < n_dis + n_gene) {
        node = w - n_dis; base = (const float4*)xd_src; csr = csr_d2g; off = off_g;
        aggp = agg_g;
    } else return;

    const int start = off[node], end = off[node + 1];
    float4 acc0 = make_float4(0.f, 0.f, 0.f, 0.f);
    float4 acc1 = make_float4(0.f, 0.f, 0.f, 0.f);
    int e = start;
    for (; e + 8 <= end; e += 8) {
        int s0 = csr[e],     s1 = csr[e + 1], s2 = csr[e + 2], s3 = csr[e + 3];
        int s4 = csr[e + 4], s5 = csr[e + 5], s6 = csr[e + 6], s7 = csr[e + 7];
        float4 a = base[(size_t)s0 * 32 + lane];
        float4 b = base[(size_t)s1 * 32 + lane];
        float4 c = base[(size_t)s2 * 32 + lane];
        float4 d = base[(size_t)s3 * 32 + lane];
        float4 p = base[(size_t)s4 * 32 + lane];
        float4 q = base[(size_t)s5 * 32 + lane];
        float4 r = base[(size_t)s6 * 32 + lane];
        float4 s = base[(size_t)s7 * 32 + lane];
        acc0.x += a.x + b.x; acc0.y += a.y + b.y; acc0.z += a.z + b.z; acc0.w += a.w + b.w;
        acc1.x += c.x + d.x; acc1.y += c.y + d.y; acc1.z += c.z + d.z; acc1.w += c.w + d.w;
        acc0.x += p.x + q.x; acc0.y += p.y + q.y; acc0.z += p.z + q.z; acc0.w += p.w + q.w;
        acc1.x += r.x + s.x; acc1.y += r.y + s.y; acc1.z += r.z + s.z; acc1.w += r.w + s.w;
    }
    for (; e + 2 <= end; e += 2) {
        float4 a = base[(size_t)csr[e] * 32 + lane];
        float4 b = base[(size_t)csr[e + 1] * 32 + lane];
        acc0.x += a.x; acc0.y += a.y; acc0.z += a.z; acc0.w += a.w;
        acc1.x += b.x; acc1.y += b.y; acc1.z += b.z; acc1.w += b.w;
    }
    if (e < end) {
        float4 a = base[(size_t)csr[e] * 32 + lane];
        acc0.x += a.x; acc0.y += a.y; acc0.z += a.z; acc0.w += a.w;
    }
    float inv = 1.0f / fmaxf((float)(end - start), 1.0f);
    float4 o;
    o.x = (acc0.x + acc1.x) * inv;
    o.y = (acc0.y + acc1.y) * inv;
    o.z = (acc0.z + acc1.z) * inv;
    o.w = (acc0.w + acc1.w) * inv;
    ((float4*)aggp)[(size_t)node * 32 + lane] = o;
}

// bf16 hi/lo images of all 8 weight matrices (plain row-major)
__global__ void prep_w_kernel(const float* __restrict__ Wl, const float* __restrict__ Wr) {
    int mat = blockIdx.x;
    int lt = mat >> 1, which = mat & 1;
    const float* W = (which ? Wr : Wl) + (size_t)lt * DIM * DIM;
    __nv_bfloat16* ih = g_wimg[mat * 2 + 0];
    __nv_bfloat16* il = g_wimg[mat * 2 + 1];
    for (int i = threadIdx.x; i < DIM * DIM; i += blockDim.x) {
        float w = W[i];
        __nv_bfloat16 h = __float2bfloat16(w);
        ih[i] = h;
        il[i] = __float2bfloat16(w - __bfloat162float(h));
    }
}

// ---------------------------------------------------------------------------
// fused update: blocks [0,nbd) -> disease, [nbd,nbd+nbg) -> gene.
// ---------------------------------------------------------------------------
#define ZSTRIDE 136
#define TILE_B  (128 * ZSTRIDE * 2)
#define OFF_BIAS 0
#define OFF_ZH   1024
#define OFF_ZL   (OFF_ZH + TILE_B)
#define OFF_WH   (OFF_ZL + TILE_B)
#define OFF_WL   (OFF_WH + TILE_B)
#define SMEM_TOT (OFF_WL + TILE_B)
#define HSTRIDE  132

__global__ void __launch_bounds__(256)
update_fused_kernel(const float* __restrict__ agg_d, const float* __restrict__ xin_d,
                    float* __restrict__ xout_d, int n_d,
                    const float* __restrict__ agg_g, const float* __restrict__ xin_g,
                    float* __restrict__ xout_g, int n_g,
                    const __nv_bfloat16* __restrict__ wimg, const float* __restrict__ bias_base,
                    int layer, int nbd, int do_relu) {
    extern __shared__ __align__(16) unsigned char smem[];
    const uint32_t sbase = smem_u32(smem);
    const int t    = threadIdx.x;
    const int wid  = t >> 5;
    const int lane = t & 31;
    const int wm   = wid >> 1;
    const int wn   = wid & 1;
    const int r0   = wm * 32;

    const int is_g = (blockIdx.x >= nbd) ? 1 : 0;
    const int tile = (is_g ? (blockIdx.x - nbd) : blockIdx.x) * 128;
    const float* agg  = is_g ? agg_g : agg_d;
    const float* xin  = is_g ? xin_g : xin_d;
    float*       xout = is_g ? xout_g : xout_d;
    const int n = is_g ? n_g : n_d;
    const int lt = layer * 2 + is_g;
    const __nv_bfloat16* wl_hi = wimg + (size_t)(lt * 4 + 0) * DIM * DIM;
    const __nv_bfloat16* wl_lo = wimg + (size_t)(lt * 4 + 1) * DIM * DIM;
    const __nv_bfloat16* wr_hi = wimg + (size_t)(lt * 4 + 2) * DIM * DIM;
    const __nv_bfloat16* wr_lo = wimg + (size_t)(lt * 4 + 3) * DIM * DIM;
    const float* bias = bias_base + (size_t)lt * DIM;

    float* sbias = (float*)(smem + OFF_BIAS);
    if (t < 128) sbias[t] = bias[t];

    const uint32_t aoff =
        ((uint32_t)((r0 + ((lane >> 3) & 1) * 8 + (lane & 7)) * ZSTRIDE +
                    ((lane >> 4) & 1) * 8)) * 2;
    const uint32_t boff =
        ((uint32_t)((wn * 64 + ((lane >> 4) & 1) * 8 + (lane & 7)) * ZSTRIDE +
                    ((lane >> 3) & 1) * 8)) * 2;

    float acc[2][8][4];
#pragma unroll
    for (int f = 0; f < 2; f++)
#pragma unroll
        for (int j = 0; j < 8; j++)
#pragma unroll
            for (int c = 0; c < 4; c++) acc[f][j][c] = 0.0f;

    for (int phase = 0; phase < 2; phase++) {
        {
            const int k = t & 127;
            __nv_bfloat16* zh = (__nv_bfloat16*)(smem + OFF_ZH);
            __nv_bfloat16* zl = (__nv_bfloat16*)(smem + OFF_ZL);
            const float* zsrc = (phase == 0) ? agg : xin;
            for (int row = (t >> 7); row < 128; row += 2) {
                int ng = tile + row;
                float v = (ng < n) ? zsrc[(size_t)ng * DIM + k] : 0.0f;
                __nv_bfloat16 h = __float2bfloat16(v);
                zh[row * ZSTRIDE + k] = h;
                zl[row * ZSTRIDE + k] = __float2bfloat16(v - __bfloat162float(h));
            }
        }
        {
            const uint4* gh = (const uint4*)(phase == 0 ? wl_hi : wr_hi);
            const uint4* gl = (const uint4*)(phase == 0 ? wl_lo : wr_lo);
            for (int i = t; i < 2048; i += 256) {
                int j = i >> 4, kc = i & 15;
                uint32_t off = ((uint32_t)(j * ZSTRIDE + kc * 8)) * 2;
                *(uint4*)(smem + OFF_WH + off) = gh[i];
                *(uint4*)(smem + OFF_WL + off) = gl[i];
            }
        }
        __syncthreads();

        const uint32_t zh_a = sbase + OFF_ZH + aoff;
        const uint32_t wh_b = sbase + OFF_WH + boff;

#pragma unroll
        for (int ks = 0; ks < 8; ks++) {
            uint32_t azh[2][4], azl[2][4], bh[4][4], bl[4][4];
#pragma unroll
            for (int f = 0; f < 2; f++) {
                uint32_t a = zh_a + ks * 32 + f * (16 * ZSTRIDE * 2);
                LDMX4(azh[f], a);
                LDMX4(azl[f], a + TILE_B);
            }
#pragma unroll
            for (int q = 0; q < 4; q++) {
                uint32_t a = wh_b + ks * 32 + q * (16 * ZSTRIDE * 2);
                LDMX4(bh[q], a);
                LDMX4(bl[q], a + TILE_B);
            }
#pragma unroll
            for (int f = 0; f < 2; f++)
#pragma unroll
                for (int j = 0; j < 8; j++) {
                    const int q = j >> 1, s = (j & 1) * 2;
                    MMA16816(acc[f][j], azh[f], bh[q][s], bh[q][s + 1]);
                    MMA16816(acc[f][j], azl[f], bh[q][s], bh[q][s + 1]);
                    MMA16816(acc[f][j], azh[f], bl[q][s], bl[q][s + 1]);
                }
        }
        __syncthreads();
    }

    float* sh = (float*)(smem + OFF_ZH);
#pragma unroll
    for (int f = 0; f < 2; f++) {
        int row = r0 + f * 16 + (lane >> 2);
        int col = wn * 64 + (lane & 3) * 2;
#pragma unroll
        for (int j = 0; j < 8; j++) {
            int c = col + j * 8;
            sh[row * HSTRIDE + c]           = acc[f][j][0];
            sh[row * HSTRIDE + c + 1]       = acc[f][j][1];
            sh[(row + 8) * HSTRIDE + c]     = acc[f][j][2];
            sh[(row + 8) * HSTRIDE + c + 1] = acc[f][j][3];
        }
    }
    __syncthreads();

    {
        const int row  = t >> 1;
        const int half = t & 1;
        const int c0   = half * 64;
        float ssq = 0.0f;
        float h[64];
#pragma unroll
        for (int c = 0; c < 64; c++) {
            float v = sh[row * HSTRIDE + c0 + c] + sbias[c0 + c];
            if (do_relu) v = fmaxf(v, 0.0f);
            h[c] = v;
            ssq += v * v;
        }
        ssq += __shfl_xor_sync(0xffffffffu, ssq, 1);
        float sc = 1.0f / fmaxf(sqrtf(ssq), 1e-12f);

        int node = tile + row;
        if (node < n) {
            const float4* xi = (const float4*)(xin + (size_t)node * DIM + c0);
            float4* xo = (float4*)(xout + (size_t)node * DIM + c0);
#pragma unroll
            for (int q = 0; q < 16; q++) {
                float4 o = xi[q];
                o.x += h[q * 4 + 0] * sc;
                o.y += h[q * 4 + 1] * sc;
                o.z += h[q * 4 + 2] * sc;
                o.w += h[q * 4 + 3] * sc;
                xo[q] = o;
            }
        }
    }
}

// ---------------------------------------------------------------------------
extern "C" void kernel_launch(void* const* d_in, const int* in_sizes, int n_in,
                              void* d_out, int out_size) {
    const float* x_gene  = (const float*)d_in[0];
    const float* x_dis   = (const float*)d_in[1];
    const float* Wl      = (const float*)d_in[2];
    const float* Wr      = (const float*)d_in[3];
    const float* b       = (const float*)d_in[4];
    const int*   src_g2d = (const int*)d_in[5];
    const int*   dst_g2d = (const int*)d_in[6];
    const int*   src_d2g = (const int*)d_in[7];
    const int*   dst_d2g = (const int*)d_in[8];

    const int n_gene = in_sizes[0] / DIM;
    const int n_dis  = in_sizes[1] / DIM;
    const int E1 = in_sizes[5];
    const int E2 = in_sizes[7];

    float *agg_d, *agg_g;
    int *cnt_d, *cnt_g, *off_d, *off_g, *cur_d, *cur_g, *csr_g2d, *csr_d2g;
    int *tmp, *part;
    __nv_bfloat16* wimg;
    cudaGetSymbolAddress((void**)&agg_d, g_agg_d);
    cudaGetSymbolAddress((void**)&agg_g, g_agg_g);
    cudaGetSymbolAddress((void**)&cnt_d, g_cnt_d);
    cudaGetSymbolAddress((void**)&cnt_g, g_cnt_g);
    cudaGetSymbolAddress((void**)&off_d, g_off_d);
    cudaGetSymbolAddress((void**)&off_g, g_off_g);
    cudaGetSymbolAddress((void**)&cur_d, g_cur_d);
    cudaGetSymbolAddress((void**)&cur_g, g_cur_g);
    cudaGetSymbolAddress((void**)&csr_g2d, g_csr_g2d);
    cudaGetSymbolAddress((void**)&csr_d2g, g_csr_d2g);
    cudaGetSymbolAddress((void**)&tmp, g_tmp);
    cudaGetSymbolAddress((void**)&part, g_part);
    cudaGetSymbolAddress((void**)&wimg, g_wimg);

    float* xg = (float*)d_out;
    float* xd = xg + (size_t)n_gene * DIM;

    prep_w_kernel<<<8, 256>>>(Wl, Wr);

    // ---- CSR build ----
    const int n_tot = n_dis + n_gene;
    const int nz = (n_gene > n_dis ? n_gene : n_dis);
    const int nb_scan = (n_tot + SCAN_TILE - 1) / SCAN_TILE;
    zero2_kernel<<<(nz + 255) / 256, 256>>>(cnt_d, n_dis, cnt_g, n_gene);
    count2_kernel<<<(E1 + E2 + 255) / 256, 256>>>(dst_g2d, cnt_d, E1, dst_d2g, cnt_g, E2);
    scan_p1_kernel<<<nb_scan, 1024>>>(cnt_d, n_dis, cnt_g, n_gene, tmp, part);
    scan_p2_kernel<<<1, 128>>>(part, nb_scan);
    scan_p3_kernel<<<(n_tot + 255) / 256, 256>>>(tmp, part, off_d, cur_d, n_dis,
                                                 off_g, cur_g, n_gene, E1, E2);
    fill2_kernel<<<(E1 + E2 + 255) / 256, 256>>>(src_g2d, dst_g2d, cur_d, csr_g2d, E1,
                                                 src_d2g, dst_d2g, cur_g, csr_d2g, E2);

    cudaFuncSetAttribute(update_fused_kernel,
                         cudaFuncAttributeMaxDynamicSharedMemorySize, SMEM_TOT);

    const int nbd = (n_dis + 127) / 128;
    const int nbg = (n_gene + 127) / 128;
    const int pull_blocks = ((n_dis + n_gene) * 32 + 255) / 256;

    // ---- layer 0: read inputs directly, write d_out ----
    pull_fused_kernel<<<pull_blocks, 256>>>(x_gene, x_dis, agg_d, agg_g,
                                            csr_g2d, off_d, csr_d2g, off_g,
                                            n_dis, n_gene);
    update_fused_kernel<<<nbd + nbg, 256, SMEM_TOT>>>(
        agg_d, x_dis, xd, n_dis, agg_g, x_gene, xg, n_gene,
        wimg, b, 0, nbd, 1);

    // ---- layer 1: in place on d_out ----
    pull_fused_kernel<<<pull_blocks, 256>>>(xg, xd, agg_d, agg_g,
                                            csr_g2d, off_d, csr_d2g, off_g,
                                            n_dis, n_gene);
    update_fused_kernel<<<nbd + nbg, 256, SMEM_TOT>>>(
        agg_d, xd, xd, n_dis, agg_g, xg, xg, n_gene,
        wimg, b, 1, nbd, 0);
}